// round 1
// baseline (speedup 1.0000x reference)
#include <cuda_runtime.h>
#include <math.h>

#define B_    64
#define N_    2048
#define C_    256
#define NB_   100
#define TILE  64
#define NT    (N_ / TILE)   // 32 tiles per batch row

// ---------------- scratch (device globals; no allocation) ----------------
__device__ float g_kn[NB_ * C_];                  // normalized key rows [100,256]
__device__ float g_attsum_part[B_ * NT * NB_];    // per-tile partial of sum_n mask*att
__device__ float g_maskfeat_part[B_ * NT * C_];   // per-tile partial of sum_n mask*feat
__device__ float g_masksum_part[B_ * NT];         // per-tile partial of sum_n mask

// ---------------- kernel A: kn = l2norm(base @ Wk^T + bk) ----------------
__global__ void kernA(const float* __restrict__ base,
                      const float* __restrict__ Wk,
                      const float* __restrict__ bk) {
    __shared__ float bs[C_];
    __shared__ float wk_s[C_][33];
    __shared__ float red[256];
    const int m = blockIdx.x;
    const int c = threadIdx.x;

    bs[c] = base[m * C_ + c];
    float acc = bk[c];
    for (int j0 = 0; j0 < C_; j0 += 32) {
        __syncthreads();
        for (int idx = threadIdx.x; idx < C_ * 32; idx += 256) {
            int cc = idx >> 5, jj = idx & 31;
            wk_s[cc][jj] = Wk[cc * C_ + j0 + jj];
        }
        __syncthreads();
#pragma unroll
        for (int jj = 0; jj < 32; jj++)
            acc = fmaf(bs[j0 + jj], wk_s[c][jj], acc);
    }
    red[c] = acc * acc;
    __syncthreads();
    for (int s = 128; s > 0; s >>= 1) {
        if (c < s) red[c] += red[c + s];
        __syncthreads();
    }
    float inv = 1.0f / fmaxf(sqrtf(red[0]), 1e-12f);
    g_kn[m * C_ + c] = acc * inv;
}

// ---------------- kernel B: main fused kernel ----------------
struct SmemB {
    float fs[TILE][260];     // feats tile (padded rows)
    float qs[TILE][260];     // q tile
    float lg[TILE][104];     // logits / att
    float kn_s[112][33];     // kn k-chunk (rows 100..111 zero)
    float wq_s[16][132];     // Wq k-tile (transposed)
    float mask_s[TILE];
    float rinv[TILE];
};

__global__ void __launch_bounds__(256, 1)
kernB(const float* __restrict__ feats,
      const float* __restrict__ mask,
      const float* __restrict__ Wq,
      const float* __restrict__ bq) {
    extern __shared__ float smem_raw[];
    SmemB& S = *reinterpret_cast<SmemB*>(smem_raw);

    const int tid  = threadIdx.x;
    const int tile = blockIdx.x;
    const int b    = blockIdx.y;
    const int tx   = tid & 15;   // col group
    const int ty   = tid >> 4;   // row group

    // ---- load feats tile [64,256] + mask ----
    {
        const float4* src = reinterpret_cast<const float4*>(
            feats + ((size_t)b * N_ + (size_t)tile * TILE) * C_);
        for (int idx = tid; idx < TILE * (C_ / 4); idx += 256) {
            int r = idx >> 6, c4 = idx & 63;
            float4 v = src[r * (C_ / 4) + c4];
            *reinterpret_cast<float4*>(&S.fs[r][c4 * 4]) = v;
        }
        if (tid < TILE)
            S.mask_s[tid] = mask[(size_t)b * N_ + (size_t)tile * TILE + tid];
    }

    // ---- phase 2: q = fs @ Wq^T + bq  (64 x 256, K=256) ----
    const int cl  = tid >> 1;         // col within 128-chunk for Wq staging
    const int kk0 = (tid & 1) * 8;    // k sub-offset
    for (int n0 = 0; n0 < C_; n0 += 128) {
        float acc[4][8];
#pragma unroll
        for (int i = 0; i < 4; i++)
#pragma unroll
            for (int j = 0; j < 8; j++) acc[i][j] = 0.0f;

        const float* wsrc = Wq + (size_t)(n0 + cl) * C_ + kk0;
        float4 p0 = *reinterpret_cast<const float4*>(wsrc + 0);
        float4 p1 = *reinterpret_cast<const float4*>(wsrc + 4);

        for (int k0 = 0; k0 < C_; k0 += 16) {
            __syncthreads();
            S.wq_s[kk0 + 0][cl] = p0.x; S.wq_s[kk0 + 1][cl] = p0.y;
            S.wq_s[kk0 + 2][cl] = p0.z; S.wq_s[kk0 + 3][cl] = p0.w;
            S.wq_s[kk0 + 4][cl] = p1.x; S.wq_s[kk0 + 5][cl] = p1.y;
            S.wq_s[kk0 + 6][cl] = p1.z; S.wq_s[kk0 + 7][cl] = p1.w;
            __syncthreads();
            if (k0 + 16 < C_) {   // prefetch next k-tile (overlaps compute)
                p0 = *reinterpret_cast<const float4*>(wsrc + k0 + 16);
                p1 = *reinterpret_cast<const float4*>(wsrc + k0 + 20);
            }
#pragma unroll
            for (int kk = 0; kk < 16; kk++) {
                float a[4];
#pragma unroll
                for (int i = 0; i < 4; i++) a[i] = S.fs[ty * 4 + i][k0 + kk];
                float4 b0 = *reinterpret_cast<float4*>(&S.wq_s[kk][tx * 8]);
                float4 b1 = *reinterpret_cast<float4*>(&S.wq_s[kk][tx * 8 + 4]);
                float bb[8] = {b0.x, b0.y, b0.z, b0.w, b1.x, b1.y, b1.z, b1.w};
#pragma unroll
                for (int i = 0; i < 4; i++)
#pragma unroll
                    for (int j = 0; j < 8; j++)
                        acc[i][j] = fmaf(a[i], bb[j], acc[i][j]);
            }
        }
#pragma unroll
        for (int j = 0; j < 8; j++) {
            int c = n0 + tx * 8 + j;
            float bias = bq[c];
#pragma unroll
            for (int i = 0; i < 4; i++)
                S.qs[ty * 4 + i][c] = acc[i][j] + bias;
        }
    }
    __syncthreads();

    // ---- phase 3: row inverse norms of q ----
    {
        int r = tid >> 2, s = tid & 3;
        float ss = 0.0f;
        for (int c = s; c < C_; c += 4) {
            float v = S.qs[r][c];
            ss = fmaf(v, v, ss);
        }
        ss += __shfl_xor_sync(0xffffffffu, ss, 1);
        ss += __shfl_xor_sync(0xffffffffu, ss, 2);
        if (s == 0) S.rinv[r] = 1.0f / fmaxf(sqrtf(ss), 1e-12f);
    }
    __syncthreads();

    // ---- phase 4: logits = (q @ kn^T) * rinv  (64 x 100) ----
    float acc2[4][7];
#pragma unroll
    for (int i = 0; i < 4; i++)
#pragma unroll
        for (int j = 0; j < 7; j++) acc2[i][j] = 0.0f;

    for (int k0 = 0; k0 < C_; k0 += 32) {
        __syncthreads();
        for (int idx = tid; idx < 112 * 32; idx += 256) {
            int m = idx >> 5, kk = idx & 31;
            S.kn_s[m][kk] = (m < NB_) ? g_kn[m * C_ + k0 + kk] : 0.0f;
        }
        __syncthreads();
#pragma unroll 8
        for (int kk = 0; kk < 32; kk++) {
            float a[4];
#pragma unroll
            for (int i = 0; i < 4; i++) a[i] = S.qs[ty * 4 + i][k0 + kk];
#pragma unroll
            for (int jm = 0; jm < 7; jm++) {
                float bv = S.kn_s[tx + (jm << 4)][kk];
#pragma unroll
                for (int i = 0; i < 4; i++)
                    acc2[i][jm] = fmaf(a[i], bv, acc2[i][jm]);
            }
        }
    }
    __syncthreads();
#pragma unroll
    for (int jm = 0; jm < 7; jm++) {
        int m = tx + (jm << 4);
        if (m < NB_) {
#pragma unroll
            for (int i = 0; i < 4; i++)
                S.lg[ty * 4 + i][m] = acc2[i][jm] * S.rinv[ty * 4 + i];
        }
    }
    __syncthreads();

    // ---- phase 5: softmax over m, fold in mask ----
    {
        int r = tid >> 2, s = tid & 3;
        float mx = -1e30f;
        for (int m = s; m < NB_; m += 4) mx = fmaxf(mx, S.lg[r][m]);
        mx = fmaxf(mx, __shfl_xor_sync(0xffffffffu, mx, 1));
        mx = fmaxf(mx, __shfl_xor_sync(0xffffffffu, mx, 2));
        float sum = 0.0f;
        for (int m = s; m < NB_; m += 4) {
            float e = __expf(S.lg[r][m] - mx);
            S.lg[r][m] = e;
            sum += e;
        }
        sum += __shfl_xor_sync(0xffffffffu, sum, 1);
        sum += __shfl_xor_sync(0xffffffffu, sum, 2);
        float scale = S.mask_s[r] / sum;
        for (int m = s; m < NB_; m += 4) S.lg[r][m] *= scale;
    }
    __syncthreads();

    // ---- phase 6: per-tile partials ----
    const int pbase = b * NT + tile;
    if (tid < NB_) {
        float a = 0.0f;
#pragma unroll 8
        for (int r = 0; r < TILE; r++) a += S.lg[r][tid];
        g_attsum_part[pbase * NB_ + tid] = a;
    }
    {
        float a = 0.0f;
#pragma unroll 8
        for (int r = 0; r < TILE; r++)
            a = fmaf(S.fs[r][tid], S.mask_s[r], a);
        g_maskfeat_part[pbase * C_ + tid] = a;
    }
    if (tid == 0) {
        float a = 0.0f;
        for (int r = 0; r < TILE; r++) a += S.mask_s[r];
        g_masksum_part[pbase] = a;
    }
}

// ---------------- kernel C: reduce partials + combine ----------------
__global__ void kernC(const float* __restrict__ base,
                      const float* __restrict__ w_avg,
                      const float* __restrict__ w_att,
                      float* __restrict__ out) {
    __shared__ float as_s[NB_];
    __shared__ float dsh;
    const int b = blockIdx.x;
    const int c = threadIdx.x;

    if (c == 0) {
        float s = 0.0f;
        for (int t = 0; t < NT; t++) s += g_masksum_part[b * NT + t];
        dsh = fmaxf(s, 1e-12f);
    }
    if (c < NB_) {
        float s = 0.0f;
        for (int t = 0; t < NT; t++)
            s += g_attsum_part[(b * NT + t) * NB_ + c];
        as_s[c] = s;
    }
    __syncthreads();

    float mf = 0.0f;
    for (int t = 0; t < NT; t++)
        mf += g_maskfeat_part[(b * NT + t) * C_ + c];

    float n2 = 0.0f;
#pragma unroll 4
    for (int m = 0; m < NB_; m++)
        n2 = fmaf(as_s[m], base[m * C_ + c], n2);

    float inv = 1.0f / dsh;
    out[b * C_ + c] = 0.5f * (mf * inv * w_avg[c] + n2 * inv * w_att[c]);
}

// ---------------- launch ----------------
extern "C" void kernel_launch(void* const* d_in, const int* in_sizes, int n_in,
                              void* d_out, int out_size) {
    const float* base   = (const float*)d_in[0];
    const float* feats  = (const float*)d_in[1];
    const float* mask   = (const float*)d_in[2];
    const float* Wq     = (const float*)d_in[3];
    const float* bq     = (const float*)d_in[4];
    const float* Wk     = (const float*)d_in[5];
    const float* bk     = (const float*)d_in[6];
    const float* w_avg  = (const float*)d_in[7];
    const float* w_att  = (const float*)d_in[8];
    float* out = (float*)d_out;

    cudaFuncSetAttribute(kernB, cudaFuncAttributeMaxDynamicSharedMemorySize,
                         (int)sizeof(SmemB));

    kernA<<<NB_, 256>>>(base, Wk, bk);
    kernB<<<dim3(NT, B_), 256, sizeof(SmemB)>>>(feats, mask, Wq, bq);
    kernC<<<B_, 256>>>(base, w_avg, w_att, out);
}

// round 3
// speedup vs baseline: 3.2551x; 3.2551x over previous
#include <cuda_runtime.h>
#include <cuda_bf16.h>
#include <cstdint>
#include <math.h>

#define B_    64
#define N_    2048
#define C_    256
#define NB_   100
#define MROWS 128
#define NT2   16
#define NBLK  (B_ * NT2)      // 1024
#define LDB   264             // bf16 elems per padded row
#define ROWB  (LDB * 2)       // 528 bytes per row

// ---------------- device scratch (no allocation) ----------------
__device__ __align__(16) __nv_bfloat16 g_E[256 * LDB];     // (Wq - I), bf16, [n][k]
__device__ __align__(16) __nv_bfloat16 g_knh[128 * LDB];   // kn hi, padded to 128 rows
__device__ __align__(16) __nv_bfloat16 g_knl[128 * LDB];   // kn lo
__device__ float g_kn[NB_ * C_];
__device__ float g_attsum_part[NBLK * NB_];
__device__ float g_maskfeat_part[NBLK * C_];
__device__ float g_masksum_part[NBLK];

// ---------------- helpers ----------------
__device__ __forceinline__ uint32_t smem_u32(const void* p) {
    uint32_t a;
    asm("{ .reg .u64 t; cvta.to.shared.u64 t, %1; cvt.u32.u64 %0, t; }" : "=r"(a) : "l"(p));
    return a;
}
__device__ __forceinline__ void ldsm4(uint32_t& r0, uint32_t& r1, uint32_t& r2, uint32_t& r3,
                                      uint32_t addr) {
    asm volatile("ldmatrix.sync.aligned.m8n8.x4.shared.b16 {%0,%1,%2,%3}, [%4];"
                 : "=r"(r0), "=r"(r1), "=r"(r2), "=r"(r3) : "r"(addr));
}
__device__ __forceinline__ void mma16816(float* c, uint32_t a0, uint32_t a1, uint32_t a2,
                                         uint32_t a3, uint32_t b0, uint32_t b1) {
    asm volatile("mma.sync.aligned.m16n8k16.row.col.f32.bf16.bf16.f32 "
                 "{%0,%1,%2,%3}, {%4,%5,%6,%7}, {%8,%9}, {%0,%1,%2,%3};"
                 : "+f"(c[0]), "+f"(c[1]), "+f"(c[2]), "+f"(c[3])
                 : "r"(a0), "r"(a1), "r"(a2), "r"(a3), "r"(b0), "r"(b1));
}
// split fp32 pair -> packed bf16x2 hi + lo
__device__ __forceinline__ void split2(float x, float y, uint32_t& hi, uint32_t& lo) {
    __nv_bfloat16 hx = __float2bfloat16(x);
    __nv_bfloat16 hy = __float2bfloat16(y);
    __nv_bfloat16 lx = __float2bfloat16(x - __bfloat162float(hx));
    __nv_bfloat16 ly = __float2bfloat16(y - __bfloat162float(hy));
    __nv_bfloat162 H = __halves2bfloat162(hx, hy);
    __nv_bfloat162 L = __halves2bfloat162(lx, ly);
    hi = *reinterpret_cast<uint32_t*>(&H);
    lo = *reinterpret_cast<uint32_t*>(&L);
}

// ================= kernel A: kn = l2norm(base @ Wk^T + bk) (coalesced) =================
__global__ void kernA(const float* __restrict__ base,
                      const float* __restrict__ Wk,
                      const float* __restrict__ bk) {
    __shared__ float bs[C_];
    __shared__ float ks[C_];
    __shared__ float red[C_];
    const int m = blockIdx.x, tid = threadIdx.x, wid = tid >> 5, lane = tid & 31;
    bs[tid] = base[m * C_ + tid];
    __syncthreads();
    for (int c = wid; c < C_; c += 8) {
        const float4* w = reinterpret_cast<const float4*>(Wk + (size_t)c * C_);
        float p = 0.0f;
#pragma unroll
        for (int i = 0; i < 2; i++) {
            int j = lane + i * 32;
            float4 v = w[j];
            p = fmaf(bs[4 * j + 0], v.x, p);
            p = fmaf(bs[4 * j + 1], v.y, p);
            p = fmaf(bs[4 * j + 2], v.z, p);
            p = fmaf(bs[4 * j + 3], v.w, p);
        }
#pragma unroll
        for (int o = 16; o; o >>= 1) p += __shfl_xor_sync(0xffffffffu, p, o);
        if (lane == 0) ks[c] = p + bk[c];
    }
    __syncthreads();
    red[tid] = ks[tid] * ks[tid];
    __syncthreads();
    for (int s = 128; s; s >>= 1) {
        if (tid < s) red[tid] += red[tid + s];
        __syncthreads();
    }
    g_kn[m * C_ + tid] = ks[tid] / fmaxf(sqrtf(red[0]), 1e-12f);
}

// ================= kernel Pack: E = Wq - I (bf16), kn hi/lo images =================
__global__ void kernPack(const float* __restrict__ Wq) {
    const int tid = threadIdx.x;
    if (blockIdx.x == 0) {
        for (int idx = tid; idx < 256 * LDB; idx += 256) {
            int n = idx / LDB, k = idx - n * LDB;
            float v = (k < 256) ? (Wq[n * 256 + k] - (n == k ? 1.0f : 0.0f)) : 0.0f;
            g_E[idx] = __float2bfloat16(v);
        }
    } else {
        for (int idx = tid; idx < 128 * LDB; idx += 256) {
            int n = idx / LDB, k = idx - n * LDB;
            float v = (n < NB_ && k < 256) ? g_kn[n * C_ + k] : 0.0f;
            __nv_bfloat16 h = __float2bfloat16(v);
            g_knh[idx] = h;
            g_knl[idx] = __float2bfloat16(v - __bfloat162float(h));
        }
    }
}

// ================= main kernel =================
// dyn smem: fh [128][264] bf16 | fl [128][264] bf16 | wc [128][264] bf16 (E/kn/att overlay)
#define OFF_FL 67584
#define OFF_WC 135168
#define DYN_SM 202752

__global__ void __launch_bounds__(256, 1)
kernMain(const float* __restrict__ feats,
         const float* __restrict__ mask,
         const float* __restrict__ bq) {
    extern __shared__ char sm[];
    __nv_bfloat16* fh = reinterpret_cast<__nv_bfloat16*>(sm);
    __nv_bfloat16* fl = reinterpret_cast<__nv_bfloat16*>(sm + OFF_FL);
    __nv_bfloat16* wc = reinterpret_cast<__nv_bfloat16*>(sm + OFF_WC);
    float* att = reinterpret_cast<float*>(sm + OFF_WC);   // [128][104] overlay
    __shared__ float mask_s[MROWS];
    __shared__ float bq_s[C_];
    __shared__ float rinv_s[MROWS];
    __shared__ float ssq_s[MROWS][4];

    const int tid = threadIdx.x, wid = tid >> 5, lane = tid & 31;
    const int blk = blockIdx.x, b = blk >> 4, n0 = (blk & 15) * MROWS;
    const int wm = wid & 1;      // M half (64 rows)
    const int wn = wid >> 1;     // N quarter
    const uint32_t FH = smem_u32(fh), FL = smem_u32(fl), WC = smem_u32(wc);

    // ---- phase 1: feats -> bf16 hi/lo in smem ----
    {
        const int r = tid >> 1, h = tid & 1;
        const float4* src = reinterpret_cast<const float4*>(
            feats + ((size_t)b * N_ + n0 + r) * C_ + h * 128);
        uint32_t* dh = reinterpret_cast<uint32_t*>(fh + r * LDB + h * 128);
        uint32_t* dl = reinterpret_cast<uint32_t*>(fl + r * LDB + h * 128);
#pragma unroll
        for (int i = 0; i < 32; i++) {
            float4 v = src[i];
            uint32_t hA, lA, hB, lB;
            split2(v.x, v.y, hA, lA);
            split2(v.z, v.w, hB, lB);
            dh[2 * i] = hA; dh[2 * i + 1] = hB;
            dl[2 * i] = lA; dl[2 * i + 1] = lB;
        }
    }
    if (tid < MROWS) mask_s[tid] = mask[(size_t)b * N_ + n0 + tid];
    bq_s[tid] = bq[tid];
    __syncthreads();

    // ---- phase 1b: maskfeat partials (threads 0-127) || E chunk0 copy (128-255) ----
    if (tid < 128) {
        float a0 = 0.0f, a1 = 0.0f;
        for (int r = 0; r < MROWS; r++) {
            float m = mask_s[r];
            uint32_t hp = reinterpret_cast<uint32_t*>(fh + r * LDB)[tid];
            uint32_t lp = reinterpret_cast<uint32_t*>(fl + r * LDB)[tid];
            __nv_bfloat162 h2 = *reinterpret_cast<__nv_bfloat162*>(&hp);
            __nv_bfloat162 l2 = *reinterpret_cast<__nv_bfloat162*>(&lp);
            a0 = fmaf(m, __bfloat162float(h2.x) + __bfloat162float(l2.x), a0);
            a1 = fmaf(m, __bfloat162float(h2.y) + __bfloat162float(l2.y), a1);
        }
        g_maskfeat_part[blk * C_ + 2 * tid]     = a0;
        g_maskfeat_part[blk * C_ + 2 * tid + 1] = a1;
        if (tid == 0) {
            float s = 0.0f;
            for (int r = 0; r < MROWS; r++) s += mask_s[r];
            g_masksum_part[blk] = s;
        }
    } else {
        const int t = tid - 128;
        const uint4* s = reinterpret_cast<const uint4*>(g_E);
        uint4* d = reinterpret_cast<uint4*>(wc);
        for (int i = t; i < 4224; i += 128) d[i] = s[i];
    }
    __syncthreads();

    // ---- phase 2: q GEMM  C1 = feats_hi @ E^T  (M128 x N256, K256) ----
    float acc[2][4][4][4];
#pragma unroll
    for (int nc = 0; nc < 2; nc++)
#pragma unroll
        for (int mt = 0; mt < 4; mt++)
#pragma unroll
            for (int nt = 0; nt < 4; nt++)
#pragma unroll
                for (int j = 0; j < 4; j++) acc[nc][mt][nt][j] = 0.0f;

    for (int nc = 0; nc < 2; nc++) {
        if (nc == 1) {
            __syncthreads();
            const uint4* s = reinterpret_cast<const uint4*>(g_E + 128 * LDB);
            uint4* d = reinterpret_cast<uint4*>(wc);
            for (int i = tid; i < 4224; i += 256) d[i] = s[i];
            __syncthreads();
        }
#pragma unroll 4
        for (int k0 = 0; k0 < 256; k0 += 16) {
            uint32_t a[4][4];
#pragma unroll
            for (int mt = 0; mt < 4; mt++) {
                uint32_t addr = FH + (uint32_t)(wm * 64 + mt * 16 + (lane & 15)) * ROWB
                              + (uint32_t)(k0 + (lane >> 4) * 8) * 2u;
                ldsm4(a[mt][0], a[mt][1], a[mt][2], a[mt][3], addr);
            }
            uint32_t bf[2][4];
#pragma unroll
            for (int np = 0; np < 2; np++) {
                uint32_t addr = WC + (uint32_t)(wn * 32 + np * 16 + (lane >> 4) * 8 + (lane & 7)) * ROWB
                              + (uint32_t)(k0 + ((lane >> 3) & 1) * 8) * 2u;
                ldsm4(bf[np][0], bf[np][1], bf[np][2], bf[np][3], addr);
            }
#pragma unroll
            for (int mt = 0; mt < 4; mt++)
#pragma unroll
                for (int nt = 0; nt < 4; nt++)
                    mma16816(acc[nc][mt][nt], a[mt][0], a[mt][1], a[mt][2], a[mt][3],
                             bf[nt >> 1][(nt & 1) * 2], bf[nt >> 1][(nt & 1) * 2 + 1]);
        }
    }
    __syncthreads();

    // ---- phase 3: q epilogue: q = C1 + (hi+lo) + bq, ssq, re-split in place ----
    {
        float ssq[4][2];
#pragma unroll
        for (int mt = 0; mt < 4; mt++) { ssq[mt][0] = 0.0f; ssq[mt][1] = 0.0f; }
#pragma unroll
        for (int nc = 0; nc < 2; nc++)
#pragma unroll
            for (int mt = 0; mt < 4; mt++)
#pragma unroll
                for (int nt = 0; nt < 4; nt++) {
                    const int n  = nc * 128 + wn * 32 + nt * 8 + (lane & 3) * 2;
                    const int m0 = wm * 64 + mt * 16 + (lane >> 2);
#pragma unroll
                    for (int hh = 0; hh < 2; hh++) {
                        const int m = m0 + hh * 8;
                        uint32_t* ph = reinterpret_cast<uint32_t*>(fh + m * LDB + n);
                        uint32_t* pl = reinterpret_cast<uint32_t*>(fl + m * LDB + n);
                        uint32_t hp = *ph, lp = *pl;
                        __nv_bfloat162 h2 = *reinterpret_cast<__nv_bfloat162*>(&hp);
                        __nv_bfloat162 l2 = *reinterpret_cast<__nv_bfloat162*>(&lp);
                        float q0 = acc[nc][mt][nt][hh * 2]     + __bfloat162float(h2.x)
                                 + __bfloat162float(l2.x) + bq_s[n];
                        float q1 = acc[nc][mt][nt][hh * 2 + 1] + __bfloat162float(h2.y)
                                 + __bfloat162float(l2.y) + bq_s[n + 1];
                        ssq[mt][hh] = fmaf(q0, q0, fmaf(q1, q1, ssq[mt][hh]));
                        uint32_t qh, ql;
                        split2(q0, q1, qh, ql);
                        *ph = qh; *pl = ql;
                    }
                }
#pragma unroll
        for (int mt = 0; mt < 4; mt++)
#pragma unroll
            for (int hh = 0; hh < 2; hh++) {
                float v = ssq[mt][hh];
                v += __shfl_xor_sync(0xffffffffu, v, 1);
                v += __shfl_xor_sync(0xffffffffu, v, 2);
                if ((lane & 3) == 0)
                    ssq_s[wm * 64 + mt * 16 + (lane >> 2) + hh * 8][wn] = v;
            }
    }
    __syncthreads();

    // ---- rinv (0-127) || kn chunk0 copy (128-255) ----
    if (tid < 128) {
        float s = ssq_s[tid][0] + ssq_s[tid][1] + ssq_s[tid][2] + ssq_s[tid][3];
        rinv_s[tid] = 1.0f / fmaxf(sqrtf(s), 1e-12f);
    } else {
        const int t = tid - 128;
        uint4* d = reinterpret_cast<uint4*>(wc);
        const uint4* sh = reinterpret_cast<const uint4*>(g_knh);
        const uint4* sl = reinterpret_cast<const uint4*>(g_knl);
        for (int i = t; i < 2112; i += 128) d[i] = sh[i];
        for (int i = t; i < 2112; i += 128) d[2112 + i] = sl[i];
    }
    __syncthreads();

    // ---- phase 4: logits GEMM, 3-product bf16 split ----
    float acc2[2][4][2][4];
#pragma unroll
    for (int lc = 0; lc < 2; lc++)
#pragma unroll
        for (int mt = 0; mt < 4; mt++)
#pragma unroll
            for (int nt = 0; nt < 2; nt++)
#pragma unroll
                for (int j = 0; j < 4; j++) acc2[lc][mt][nt][j] = 0.0f;

    for (int lc = 0; lc < 2; lc++) {
        if (lc == 1) {
            __syncthreads();
            uint4* d = reinterpret_cast<uint4*>(wc);
            const uint4* sh = reinterpret_cast<const uint4*>(g_knh);
            const uint4* sl = reinterpret_cast<const uint4*>(g_knl);
            for (int i = tid; i < 2112; i += 256) { d[i] = sh[2112 + i]; d[2112 + i] = sl[2112 + i]; }
            __syncthreads();
        }
#pragma unroll 2
        for (int k0 = 0; k0 < 256; k0 += 16) {
            uint32_t ah[4][4], al[4][4];
#pragma unroll
            for (int mt = 0; mt < 4; mt++) {
                uint32_t ro = (uint32_t)(wm * 64 + mt * 16 + (lane & 15)) * ROWB
                            + (uint32_t)(k0 + (lane >> 4) * 8) * 2u;
                ldsm4(ah[mt][0], ah[mt][1], ah[mt][2], ah[mt][3], FH + ro);
                ldsm4(al[mt][0], al[mt][1], al[mt][2], al[mt][3], FL + ro);
            }
            uint32_t bh[4], bl[4];
            {
                uint32_t addr = WC + (uint32_t)(wn * 16 + (lane >> 4) * 8 + (lane & 7)) * ROWB
                              + (uint32_t)(k0 + ((lane >> 3) & 1) * 8) * 2u;
                ldsm4(bh[0], bh[1], bh[2], bh[3], addr);
                ldsm4(bl[0], bl[1], bl[2], bl[3], addr + 64u * ROWB);
            }
#pragma unroll
            for (int mt = 0; mt < 4; mt++)
#pragma unroll
                for (int nt = 0; nt < 2; nt++) {
                    float* c = acc2[lc][mt][nt];
                    mma16816(c, ah[mt][0], ah[mt][1], ah[mt][2], ah[mt][3], bh[nt*2], bh[nt*2+1]);
                    mma16816(c, al[mt][0], al[mt][1], al[mt][2], al[mt][3], bh[nt*2], bh[nt*2+1]);
                    mma16816(c, ah[mt][0], ah[mt][1], ah[mt][2], ah[mt][3], bl[nt*2], bl[nt*2+1]);
                }
        }
    }
    __syncthreads();

    // ---- phase 5: logits epilogue -> att smem (scaled by rinv) ----
#pragma unroll
    for (int lc = 0; lc < 2; lc++)
#pragma unroll
        for (int mt = 0; mt < 4; mt++)
#pragma unroll
            for (int nt = 0; nt < 2; nt++) {
                const int n  = lc * 64 + wn * 16 + nt * 8 + (lane & 3) * 2;
                const int m0 = wm * 64 + mt * 16 + (lane >> 2);
                if (n < 104) {
#pragma unroll
                    for (int hh = 0; hh < 2; hh++) {
                        const int m = m0 + hh * 8;
                        const float ri = rinv_s[m];
                        att[m * 104 + n]     = acc2[lc][mt][nt][hh * 2]     * ri;
                        att[m * 104 + n + 1] = acc2[lc][mt][nt][hh * 2 + 1] * ri;
                    }
                }
            }
    __syncthreads();

    // ---- phase 6: softmax + mask fold (one thread per row) ----
    if (tid < MROWS) {
        float* row = att + tid * 104;
        float mx = -1e30f;
#pragma unroll 4
        for (int j = 0; j < NB_; j++) mx = fmaxf(mx, row[j]);
        float s = 0.0f;
#pragma unroll 4
        for (int j = 0; j < NB_; j++) { float e = __expf(row[j] - mx); row[j] = e; s += e; }
        const float sc = mask_s[tid] / s;
#pragma unroll 4
        for (int j = 0; j < NB_; j++) row[j] *= sc;
    }
    __syncthreads();

    // ---- phase 7: attsum partials ----
    if (tid < NB_) {
        float a = 0.0f;
#pragma unroll 8
        for (int r = 0; r < MROWS; r++) a += att[r * 104 + tid];
        g_attsum_part[blk * NB_ + tid] = a;
    }
}

// ================= kernel C: reduce partials + combine =================
__global__ void kernC(const float* __restrict__ base,
                      const float* __restrict__ w_avg,
                      const float* __restrict__ w_att,
                      float* __restrict__ out) {
    __shared__ float as_s[NB_];
    __shared__ float dsh;
    const int b = blockIdx.x, c = threadIdx.x;

    if (c == 0) {
        float s = 0.0f;
        for (int t = 0; t < NT2; t++) s += g_masksum_part[b * NT2 + t];
        dsh = fmaxf(s, 1e-12f);
    }
    if (c < NB_) {
        float s = 0.0f;
        for (int t = 0; t < NT2; t++) s += g_attsum_part[(b * NT2 + t) * NB_ + c];
        as_s[c] = s;
    }
    __syncthreads();

    float mf = 0.0f;
    for (int t = 0; t < NT2; t++) mf += g_maskfeat_part[(b * NT2 + t) * C_ + c];

    float n2 = 0.0f;
#pragma unroll 4
    for (int m = 0; m < NB_; m++) n2 = fmaf(as_s[m], base[m * C_ + c], n2);

    float inv = 1.0f / dsh;
    out[b * C_ + c] = 0.5f * (mf * inv * w_avg[c] + n2 * inv * w_att[c]);
}

// ================= launch =================
extern "C" void kernel_launch(void* const* d_in, const int* in_sizes, int n_in,
                              void* d_out, int out_size) {
    const float* base  = (const float*)d_in[0];
    const float* feats = (const float*)d_in[1];
    const float* mask  = (const float*)d_in[2];
    const float* Wq    = (const float*)d_in[3];
    const float* bq    = (const float*)d_in[4];
    const float* Wk    = (const float*)d_in[5];
    const float* bk    = (const float*)d_in[6];
    const float* w_avg = (const float*)d_in[7];
    const float* w_att = (const float*)d_in[8];
    float* out = (float*)d_out;

    cudaFuncSetAttribute(kernMain, cudaFuncAttributeMaxDynamicSharedMemorySize, DYN_SM);

    kernA<<<NB_, 256>>>(base, Wk, bk);
    kernPack<<<2, 256>>>(Wq);
    kernMain<<<NBLK, 256, DYN_SM>>>(feats, mask, bq);
    kernC<<<B_, 256>>>(base, w_avg, w_att, out);
}

// round 5
// speedup vs baseline: 3.7190x; 1.1425x over previous
#include <cuda_runtime.h>
#include <cuda_bf16.h>
#include <cstdint>
#include <math.h>

#define B_    64
#define N_    2048
#define C_    256
#define NB_   100
#define MROWS 128
#define NT2   16
#define NBLK  (B_ * NT2)      // 1024
#define LDB   264             // bf16 elems per padded row
#define ROWB  (LDB * 2)       // 528 bytes per row

// ---------------- device scratch (no allocation) ----------------
__device__ __align__(16) __nv_bfloat16 g_E[256 * LDB];     // (Wq - I), bf16, [n][k]
__device__ __align__(16) __nv_bfloat16 g_knh[128 * LDB];   // kn hi, padded to 128 rows
__device__ __align__(16) __nv_bfloat16 g_knl[128 * LDB];   // kn lo
__device__ float g_kn[NB_ * C_];
__device__ float g_attsum_part[NBLK * NB_];
__device__ float g_maskfeat_part[NBLK * C_];
__device__ float g_masksum_part[NBLK];

// ---------------- helpers ----------------
__device__ __forceinline__ uint32_t smem_u32(const void* p) {
    uint32_t a;
    asm("{ .reg .u64 t; cvta.to.shared.u64 t, %1; cvt.u32.u64 %0, t; }" : "=r"(a) : "l"(p));
    return a;
}
__device__ __forceinline__ void ldsm4(uint32_t& r0, uint32_t& r1, uint32_t& r2, uint32_t& r3,
                                      uint32_t addr) {
    asm volatile("ldmatrix.sync.aligned.m8n8.x4.shared.b16 {%0,%1,%2,%3}, [%4];"
                 : "=r"(r0), "=r"(r1), "=r"(r2), "=r"(r3) : "r"(addr));
}
__device__ __forceinline__ void mma16816(float* c, uint32_t a0, uint32_t a1, uint32_t a2,
                                         uint32_t a3, uint32_t b0, uint32_t b1) {
    asm volatile("mma.sync.aligned.m16n8k16.row.col.f32.bf16.bf16.f32 "
                 "{%0,%1,%2,%3}, {%4,%5,%6,%7}, {%8,%9}, {%0,%1,%2,%3};"
                 : "+f"(c[0]), "+f"(c[1]), "+f"(c[2]), "+f"(c[3])
                 : "r"(a0), "r"(a1), "r"(a2), "r"(a3), "r"(b0), "r"(b1));
}
__device__ __forceinline__ void split2(float x, float y, uint32_t& hi, uint32_t& lo) {
    __nv_bfloat16 hx = __float2bfloat16(x);
    __nv_bfloat16 hy = __float2bfloat16(y);
    __nv_bfloat16 lx = __float2bfloat16(x - __bfloat162float(hx));
    __nv_bfloat16 ly = __float2bfloat16(y - __bfloat162float(hy));
    __nv_bfloat162 H = __halves2bfloat162(hx, hy);
    __nv_bfloat162 L = __halves2bfloat162(lx, ly);
    hi = *reinterpret_cast<uint32_t*>(&H);
    lo = *reinterpret_cast<uint32_t*>(&L);
}

// ================= kernel A: kn = l2norm(base @ Wk^T + bk) =================
__global__ void kernA(const float* __restrict__ base,
                      const float* __restrict__ Wk,
                      const float* __restrict__ bk) {
    __shared__ float bs[C_];
    __shared__ float ks[C_];
    __shared__ float red[C_];
    const int m = blockIdx.x, tid = threadIdx.x, wid = tid >> 5, lane = tid & 31;
    bs[tid] = base[m * C_ + tid];
    __syncthreads();
    for (int c = wid; c < C_; c += 8) {
        const float4* w = reinterpret_cast<const float4*>(Wk + (size_t)c * C_);
        float p = 0.0f;
#pragma unroll
        for (int i = 0; i < 2; i++) {
            int j = lane + i * 32;
            float4 v = w[j];
            p = fmaf(bs[4 * j + 0], v.x, p);
            p = fmaf(bs[4 * j + 1], v.y, p);
            p = fmaf(bs[4 * j + 2], v.z, p);
            p = fmaf(bs[4 * j + 3], v.w, p);
        }
#pragma unroll
        for (int o = 16; o; o >>= 1) p += __shfl_xor_sync(0xffffffffu, p, o);
        if (lane == 0) ks[c] = p + bk[c];
    }
    __syncthreads();
    red[tid] = ks[tid] * ks[tid];
    __syncthreads();
    for (int s = 128; s; s >>= 1) {
        if (tid < s) red[tid] += red[tid + s];
        __syncthreads();
    }
    g_kn[m * C_ + tid] = ks[tid] / fmaxf(sqrtf(red[0]), 1e-12f);
}

// ================= kernel Pack (16 blocks) =================
__global__ void kernPack(const float* __restrict__ Wq) {
    const int tid = threadIdx.x, bb = blockIdx.x;
    if (bb < 8) {
        for (int idx = bb * 256 + tid; idx < 256 * LDB; idx += 2048) {
            int n = idx / LDB, k = idx - n * LDB;
            float v = (k < 256) ? (Wq[n * 256 + k] - (n == k ? 1.0f : 0.0f)) : 0.0f;
            g_E[idx] = __float2bfloat16(v);
        }
    } else {
        for (int idx = (bb - 8) * 256 + tid; idx < 128 * LDB; idx += 2048) {
            int n = idx / LDB, k = idx - n * LDB;
            float v = (n < NB_ && k < 256) ? g_kn[n * C_ + k] : 0.0f;
            __nv_bfloat16 h = __float2bfloat16(v);
            g_knh[idx] = h;
            g_knl[idx] = __float2bfloat16(v - __bfloat162float(h));
        }
    }
}

// ================= main kernel (512 threads) =================
#define OFF_FL 67584
#define OFF_WC 135168
#define DYN_SM 202752

__global__ void __launch_bounds__(512, 1)
kernMain(const float* __restrict__ feats,
         const float* __restrict__ mask,
         const float* __restrict__ bq) {
    extern __shared__ char sm[];
    __nv_bfloat16* fh = reinterpret_cast<__nv_bfloat16*>(sm);
    __nv_bfloat16* fl = reinterpret_cast<__nv_bfloat16*>(sm + OFF_FL);
    __nv_bfloat16* wc = reinterpret_cast<__nv_bfloat16*>(sm + OFF_WC);
    float* att = reinterpret_cast<float*>(sm + OFF_WC);
    __shared__ float mask_s[MROWS];
    __shared__ float bq_s[C_];
    __shared__ float rinv_s[MROWS];
    __shared__ float ssq_s[MROWS][4];
    __shared__ float mf_s[2][256];
    __shared__ float as4[4][104];

    const int tid = threadIdx.x, wid = tid >> 5, lane = tid & 31;
    const int blk = blockIdx.x, b = blk >> 4, n0 = (blk & 15) * MROWS;
    const int wm = wid & 3;      // M block of 32 rows
    const int wn = wid >> 2;     // N block
    const uint32_t FH = smem_u32(fh), FL = smem_u32(fl), WC = smem_u32(wc);

    // ---- phase 1: feats -> bf16 hi/lo in smem (512 thr, 64 cols each) ----
    {
        const int r = tid >> 2, seg = tid & 3;
        const float4* src = reinterpret_cast<const float4*>(
            feats + ((size_t)b * N_ + n0 + r) * C_ + seg * 64);
        uint32_t* dh = reinterpret_cast<uint32_t*>(fh + r * LDB + seg * 64);
        uint32_t* dl = reinterpret_cast<uint32_t*>(fl + r * LDB + seg * 64);
#pragma unroll
        for (int i = 0; i < 16; i++) {
            float4 v = src[i];
            uint32_t hA, lA, hB, lB;
            split2(v.x, v.y, hA, lA);
            split2(v.z, v.w, hB, lB);
            dh[2 * i] = hA; dh[2 * i + 1] = hB;
            dl[2 * i] = lA; dl[2 * i + 1] = lB;
        }
    }
    if (tid < MROWS) mask_s[tid] = mask[(size_t)b * N_ + n0 + tid];
    if (tid < C_) bq_s[tid] = bq[tid];
    __syncthreads();

    // ---- phase 1b: maskfeat partials (thr 0-255, row-split 2) || E chunk0 (256-511) ----
    if (tid < 256) {
        const int cp = tid & 127, half = tid >> 7;
        float a0 = 0.0f, a1 = 0.0f;
#pragma unroll 8
        for (int r = half * 64; r < half * 64 + 64; r++) {
            float m = mask_s[r];
            uint32_t hp = reinterpret_cast<uint32_t*>(fh + r * LDB)[cp];
            uint32_t lp = reinterpret_cast<uint32_t*>(fl + r * LDB)[cp];
            __nv_bfloat162 h2 = *reinterpret_cast<__nv_bfloat162*>(&hp);
            __nv_bfloat162 l2 = *reinterpret_cast<__nv_bfloat162*>(&lp);
            a0 = fmaf(m, __bfloat162float(h2.x) + __bfloat162float(l2.x), a0);
            a1 = fmaf(m, __bfloat162float(h2.y) + __bfloat162float(l2.y), a1);
        }
        mf_s[half][2 * cp]     = a0;
        mf_s[half][2 * cp + 1] = a1;
        if (tid == 0) {
            float s = 0.0f;
            for (int r = 0; r < MROWS; r++) s += mask_s[r];
            g_masksum_part[blk] = s;
        }
    } else {
        const int t = tid - 256;
        const uint4* s = reinterpret_cast<const uint4*>(g_E);
        uint4* d = reinterpret_cast<uint4*>(wc);
        for (int i = t; i < 4224; i += 256) d[i] = s[i];
    }
    __syncthreads();
    if (tid < 256)
        g_maskfeat_part[blk * C_ + tid] = mf_s[0][tid] + mf_s[1][tid];

    // ---- phase 2: q GEMM  C1 = feats_hi @ E^T  (M128 x N256, K256) ----
    float acc[2][2][4][4];
#pragma unroll
    for (int nc = 0; nc < 2; nc++)
#pragma unroll
        for (int mt = 0; mt < 2; mt++)
#pragma unroll
            for (int nt = 0; nt < 4; nt++)
#pragma unroll
                for (int j = 0; j < 4; j++) acc[nc][mt][nt][j] = 0.0f;

    for (int nc = 0; nc < 2; nc++) {
        if (nc == 1) {
            __syncthreads();
            const uint4* s = reinterpret_cast<const uint4*>(g_E + 128 * LDB);
            uint4* d = reinterpret_cast<uint4*>(wc);
            for (int i = tid; i < 4224; i += 512) d[i] = s[i];
            __syncthreads();
        }
#pragma unroll 4
        for (int k0 = 0; k0 < 256; k0 += 16) {
            uint32_t a[2][4];
#pragma unroll
            for (int mt = 0; mt < 2; mt++) {
                uint32_t addr = FH + (uint32_t)(wm * 32 + mt * 16 + (lane & 15)) * ROWB
                              + (uint32_t)(k0 + (lane >> 4) * 8) * 2u;
                ldsm4(a[mt][0], a[mt][1], a[mt][2], a[mt][3], addr);
            }
            uint32_t bf[2][4];
#pragma unroll
            for (int np = 0; np < 2; np++) {
                uint32_t addr = WC + (uint32_t)(wn * 32 + np * 16 + (lane >> 4) * 8 + (lane & 7)) * ROWB
                              + (uint32_t)(k0 + ((lane >> 3) & 1) * 8) * 2u;
                ldsm4(bf[np][0], bf[np][1], bf[np][2], bf[np][3], addr);
            }
#pragma unroll
            for (int mt = 0; mt < 2; mt++)
#pragma unroll
                for (int nt = 0; nt < 4; nt++)
                    mma16816(acc[nc][mt][nt], a[mt][0], a[mt][1], a[mt][2], a[mt][3],
                             bf[nt >> 1][(nt & 1) * 2], bf[nt >> 1][(nt & 1) * 2 + 1]);
        }
    }
    __syncthreads();

    // ---- phase 3: q epilogue ----
    {
        float ssq[2][2];
#pragma unroll
        for (int mt = 0; mt < 2; mt++) { ssq[mt][0] = 0.0f; ssq[mt][1] = 0.0f; }
#pragma unroll
        for (int nc = 0; nc < 2; nc++)
#pragma unroll
            for (int mt = 0; mt < 2; mt++)
#pragma unroll
                for (int nt = 0; nt < 4; nt++) {
                    const int n  = nc * 128 + wn * 32 + nt * 8 + (lane & 3) * 2;
                    const int m0 = wm * 32 + mt * 16 + (lane >> 2);
#pragma unroll
                    for (int hh = 0; hh < 2; hh++) {
                        const int m = m0 + hh * 8;
                        uint32_t* ph = reinterpret_cast<uint32_t*>(fh + m * LDB + n);
                        uint32_t* pl = reinterpret_cast<uint32_t*>(fl + m * LDB + n);
                        uint32_t hp = *ph, lp = *pl;
                        __nv_bfloat162 h2 = *reinterpret_cast<__nv_bfloat162*>(&hp);
                        __nv_bfloat162 l2 = *reinterpret_cast<__nv_bfloat162*>(&lp);
                        float q0 = acc[nc][mt][nt][hh * 2]     + __bfloat162float(h2.x)
                                 + __bfloat162float(l2.x) + bq_s[n];
                        float q1 = acc[nc][mt][nt][hh * 2 + 1] + __bfloat162float(h2.y)
                                 + __bfloat162float(l2.y) + bq_s[n + 1];
                        ssq[mt][hh] = fmaf(q0, q0, fmaf(q1, q1, ssq[mt][hh]));
                        uint32_t qh, ql;
                        split2(q0, q1, qh, ql);
                        *ph = qh; *pl = ql;
                    }
                }
#pragma unroll
        for (int mt = 0; mt < 2; mt++)
#pragma unroll
            for (int hh = 0; hh < 2; hh++) {
                float v = ssq[mt][hh];
                v += __shfl_xor_sync(0xffffffffu, v, 1);
                v += __shfl_xor_sync(0xffffffffu, v, 2);
                if ((lane & 3) == 0)
                    ssq_s[wm * 32 + mt * 16 + (lane >> 2) + hh * 8][wn] = v;
            }
    }
    __syncthreads();

    // ---- rinv (0-127) || kn chunk0 copy (128-511) ----
    if (tid < 128) {
        float s = ssq_s[tid][0] + ssq_s[tid][1] + ssq_s[tid][2] + ssq_s[tid][3];
        rinv_s[tid] = 1.0f / fmaxf(sqrtf(s), 1e-12f);
    } else {
        const int t = tid - 128;
        uint4* d = reinterpret_cast<uint4*>(wc);
        const uint4* sh = reinterpret_cast<const uint4*>(g_knh);
        const uint4* sl = reinterpret_cast<const uint4*>(g_knl);
        for (int i = t; i < 2112; i += 384) d[i] = sh[i];
        for (int i = t; i < 2112; i += 384) d[2112 + i] = sl[i];
    }
    __syncthreads();

    // ---- phase 4: logits GEMM, 3-product bf16 split ----
    float acc2[2][2][2][4];
#pragma unroll
    for (int lc = 0; lc < 2; lc++)
#pragma unroll
        for (int mt = 0; mt < 2; mt++)
#pragma unroll
            for (int nt = 0; nt < 2; nt++)
#pragma unroll
                for (int j = 0; j < 4; j++) acc2[lc][mt][nt][j] = 0.0f;

    for (int lc = 0; lc < 2; lc++) {
        if (lc == 1) {
            __syncthreads();
            uint4* d = reinterpret_cast<uint4*>(wc);
            const uint4* sh = reinterpret_cast<const uint4*>(g_knh);
            const uint4* sl = reinterpret_cast<const uint4*>(g_knl);
            for (int i = tid; i < 2112; i += 512) { d[i] = sh[2112 + i]; d[2112 + i] = sl[2112 + i]; }
            __syncthreads();
        }
#pragma unroll 2
        for (int k0 = 0; k0 < 256; k0 += 16) {
            uint32_t ah[2][4], al[2][4];
#pragma unroll
            for (int mt = 0; mt < 2; mt++) {
                uint32_t ro = (uint32_t)(wm * 32 + mt * 16 + (lane & 15)) * ROWB
                            + (uint32_t)(k0 + (lane >> 4) * 8) * 2u;
                ldsm4(ah[mt][0], ah[mt][1], ah[mt][2], ah[mt][3], FH + ro);
                ldsm4(al[mt][0], al[mt][1], al[mt][2], al[mt][3], FL + ro);
            }
            uint32_t bh[4], bl[4];
            {
                uint32_t addr = WC + (uint32_t)(wn * 16 + (lane >> 4) * 8 + (lane & 7)) * ROWB
                              + (uint32_t)(k0 + ((lane >> 3) & 1) * 8) * 2u;
                ldsm4(bh[0], bh[1], bh[2], bh[3], addr);
                ldsm4(bl[0], bl[1], bl[2], bl[3], addr + 64u * ROWB);
            }
#pragma unroll
            for (int mt = 0; mt < 2; mt++)
#pragma unroll
                for (int nt = 0; nt < 2; nt++) {
                    float* c = acc2[lc][mt][nt];
                    mma16816(c, ah[mt][0], ah[mt][1], ah[mt][2], ah[mt][3], bh[nt*2], bh[nt*2+1]);
                    mma16816(c, al[mt][0], al[mt][1], al[mt][2], al[mt][3], bh[nt*2], bh[nt*2+1]);
                    mma16816(c, ah[mt][0], ah[mt][1], ah[mt][2], ah[mt][3], bl[nt*2], bl[nt*2+1]);
                }
        }
    }
    __syncthreads();

    // ---- phase 5: logits epilogue -> att smem (scaled by rinv) ----
#pragma unroll
    for (int lc = 0; lc < 2; lc++)
#pragma unroll
        for (int mt = 0; mt < 2; mt++)
#pragma unroll
            for (int nt = 0; nt < 2; nt++) {
                const int n  = lc * 64 + wn * 16 + nt * 8 + (lane & 3) * 2;
                const int m0 = wm * 32 + mt * 16 + (lane >> 2);
                if (n < 104) {
#pragma unroll
                    for (int hh = 0; hh < 2; hh++) {
                        const int m = m0 + hh * 8;
                        const float ri = rinv_s[m];
                        att[m * 104 + n]     = acc2[lc][mt][nt][hh * 2]     * ri;
                        att[m * 104 + n + 1] = acc2[lc][mt][nt][hh * 2 + 1] * ri;
                    }
                }
            }
    __syncthreads();

    // ---- phase 6: softmax + mask fold (4 threads per row) ----
    {
        const int r = tid >> 2, s = tid & 3;
        float* row = att + r * 104;
        float mx = -1e30f;
        for (int j = s; j < NB_; j += 4) mx = fmaxf(mx, row[j]);
        mx = fmaxf(mx, __shfl_xor_sync(0xffffffffu, mx, 1));
        mx = fmaxf(mx, __shfl_xor_sync(0xffffffffu, mx, 2));
        float sum = 0.0f;
        for (int j = s; j < NB_; j += 4) { float e = __expf(row[j] - mx); row[j] = e; sum += e; }
        sum += __shfl_xor_sync(0xffffffffu, sum, 1);
        sum += __shfl_xor_sync(0xffffffffu, sum, 2);
        const float sc = mask_s[r] / sum;
        for (int j = s; j < NB_; j += 4) row[j] *= sc;
    }
    __syncthreads();

    // ---- phase 7: attsum partials (row-split 4) ----
    {
        const int c = tid & 127, quarter = tid >> 7;
        if (c < 104) {
            float a = 0.0f;
#pragma unroll 8
            for (int r = quarter * 32; r < quarter * 32 + 32; r++) a += att[r * 104 + c];
            as4[quarter][c] = a;
        }
    }
    __syncthreads();
    if (tid < NB_)
        g_attsum_part[blk * NB_ + tid] = as4[0][tid] + as4[1][tid] + as4[2][tid] + as4[3][tid];
}

// ================= kernel C: reduce partials + combine (512 thr) =================
__global__ void kernC(const float* __restrict__ base,
                      const float* __restrict__ w_avg,
                      const float* __restrict__ w_att,
                      float* __restrict__ out) {
    __shared__ float as_s[NB_];
    __shared__ float mf2[2][256];
    __shared__ float as2[2][NB_];
    __shared__ float dsh;
    const int b = blockIdx.x, tid = threadIdx.x;
    const int c = tid & 255, h = tid >> 8;

    if (tid == 0) {
        float s = 0.0f;
        for (int t = 0; t < NT2; t++) s += g_masksum_part[b * NT2 + t];
        dsh = fmaxf(s, 1e-12f);
    }
    if (c < NB_) {
        float s = 0.0f;
        for (int t = h * 8; t < h * 8 + 8; t++)
            s += g_attsum_part[(b * NT2 + t) * NB_ + c];
        as2[h][c] = s;
    }
    {
        float s = 0.0f;
        for (int t = h * 8; t < h * 8 + 8; t++)
            s += g_maskfeat_part[(b * NT2 + t) * C_ + c];
        mf2[h][c] = s;
    }
    __syncthreads();
    if (tid < NB_) as_s[tid] = as2[0][tid] + as2[1][tid];
    __syncthreads();
    if (tid < 256) {
        float mf = mf2[0][tid] + mf2[1][tid];
        float n2 = 0.0f;
#pragma unroll 4
        for (int m = 0; m < NB_; m++) n2 = fmaf(as_s[m], base[m * C_ + tid], n2);
        float inv = 1.0f / dsh;
        out[b * C_ + tid] = 0.5f * (mf * inv * w_avg[tid] + n2 * inv * w_att[tid]);
    }
}

// ================= launch =================
extern "C" void kernel_launch(void* const* d_in, const int* in_sizes, int n_in,
                              void* d_out, int out_size) {
    const float* base  = (const float*)d_in[0];
    const float* feats = (const float*)d_in[1];
    const float* mask  = (const float*)d_in[2];
    const float* Wq    = (const float*)d_in[3];
    const float* bq    = (const float*)d_in[4];
    const float* Wk    = (const float*)d_in[5];
    const float* bk    = (const float*)d_in[6];
    const float* w_avg = (const float*)d_in[7];
    const float* w_att = (const float*)d_in[8];
    float* out = (float*)d_out;

    cudaFuncSetAttribute(kernMain, cudaFuncAttributeMaxDynamicSharedMemorySize, DYN_SM);

    kernA<<<NB_, 256>>>(base, Wk, bk);
    kernPack<<<16, 256>>>(Wq);
    kernMain<<<NBLK, 512, DYN_SM>>>(feats, mask, bq);
    kernC<<<B_, 512>>>(base, w_avg, w_att, out);
}

// round 6
// speedup vs baseline: 4.5210x; 1.2157x over previous
#include <cuda_runtime.h>
#include <cuda_bf16.h>
#include <cstdint>
#include <math.h>

#define B_    64
#define N_    2048
#define C_    256
#define NB_   100
#define MR    64              // rows per CTA
#define NT2   32              // tiles per batch
#define NBLK  (B_ * NT2)      // 2048
#define LDB   264             // bf16 elems per padded row
#define ROWB  (LDB * 2)       // 528 bytes

// ---------------- device scratch ----------------
__device__ __align__(16) __nv_bfloat16 g_E[256 * LDB];     // (Wq - I) bf16, [n][k]
__device__ __align__(16) __nv_bfloat16 g_kn2[128 * LDB];   // kn bf16-hi, rows 100..127 zero
__device__ float g_attsum_part[NBLK * NB_];
__device__ float g_maskfeat_part[NBLK * C_];
__device__ float g_masksum_part[NBLK];

// ---------------- helpers ----------------
__device__ __forceinline__ uint32_t smem_u32(const void* p) {
    uint32_t a;
    asm("{ .reg .u64 t; cvta.to.shared.u64 t, %1; cvt.u32.u64 %0, t; }" : "=r"(a) : "l"(p));
    return a;
}
__device__ __forceinline__ void ldsm4(uint32_t& r0, uint32_t& r1, uint32_t& r2, uint32_t& r3,
                                      uint32_t addr) {
    asm volatile("ldmatrix.sync.aligned.m8n8.x4.shared.b16 {%0,%1,%2,%3}, [%4];"
                 : "=r"(r0), "=r"(r1), "=r"(r2), "=r"(r3) : "r"(addr));
}
__device__ __forceinline__ void mma16816(float* c, uint32_t a0, uint32_t a1, uint32_t a2,
                                         uint32_t a3, uint32_t b0, uint32_t b1) {
    asm volatile("mma.sync.aligned.m16n8k16.row.col.f32.bf16.bf16.f32 "
                 "{%0,%1,%2,%3}, {%4,%5,%6,%7}, {%8,%9}, {%0,%1,%2,%3};"
                 : "+f"(c[0]), "+f"(c[1]), "+f"(c[2]), "+f"(c[3])
                 : "r"(a0), "r"(a1), "r"(a2), "r"(a3), "r"(b0), "r"(b1));
}
__device__ __forceinline__ uint32_t cvt2hi(float x, float y) {
    __nv_bfloat162 H = __halves2bfloat162(__float2bfloat16(x), __float2bfloat16(y));
    return *reinterpret_cast<uint32_t*>(&H);
}
__device__ __forceinline__ void split2(float x, float y, uint32_t& hi, uint32_t& lo) {
    __nv_bfloat16 hx = __float2bfloat16(x);
    __nv_bfloat16 hy = __float2bfloat16(y);
    __nv_bfloat16 lx = __float2bfloat16(x - __bfloat162float(hx));
    __nv_bfloat16 ly = __float2bfloat16(y - __bfloat162float(hy));
    __nv_bfloat162 H = __halves2bfloat162(hx, hy);
    __nv_bfloat162 L = __halves2bfloat162(lx, ly);
    hi = *reinterpret_cast<uint32_t*>(&H);
    lo = *reinterpret_cast<uint32_t*>(&L);
}

// ================= kernel AP: kn compute+pack (blocks 0-99), E pack (100-107), zero pad (108) =====
__global__ void kernAP(const float* __restrict__ base,
                       const float* __restrict__ Wk,
                       const float* __restrict__ bk,
                       const float* __restrict__ Wq) {
    const int bb = blockIdx.x, tid = threadIdx.x;
    if (bb < NB_) {
        __shared__ float bs[C_];
        __shared__ float ks[C_];
        __shared__ float red[C_];
        const int wid = tid >> 5, lane = tid & 31;
        bs[tid] = base[bb * C_ + tid];
        __syncthreads();
        for (int c = wid; c < C_; c += 8) {
            const float4* w = reinterpret_cast<const float4*>(Wk + (size_t)c * C_);
            float p = 0.0f;
#pragma unroll
            for (int i = 0; i < 2; i++) {
                int j = lane + i * 32;
                float4 v = w[j];
                p = fmaf(bs[4 * j + 0], v.x, p);
                p = fmaf(bs[4 * j + 1], v.y, p);
                p = fmaf(bs[4 * j + 2], v.z, p);
                p = fmaf(bs[4 * j + 3], v.w, p);
            }
#pragma unroll
            for (int o = 16; o; o >>= 1) p += __shfl_xor_sync(0xffffffffu, p, o);
            if (lane == 0) ks[c] = p + bk[c];
        }
        __syncthreads();
        red[tid] = ks[tid] * ks[tid];
        __syncthreads();
        for (int s = 128; s; s >>= 1) {
            if (tid < s) red[tid] += red[tid + s];
            __syncthreads();
        }
        float kn = ks[tid] / fmaxf(sqrtf(red[0]), 1e-12f);
        g_kn2[bb * LDB + tid] = __float2bfloat16(kn);
    } else if (bb < 108) {
        for (int idx = (bb - 100) * 256 + tid; idx < 256 * LDB; idx += 8 * 256) {
            int n = idx / LDB, k = idx - n * LDB;
            float v = (k < 256) ? (Wq[n * 256 + k] - (n == k ? 1.0f : 0.0f)) : 0.0f;
            g_E[idx] = __float2bfloat16(v);
        }
    } else {
        for (int idx = tid; idx < 28 * LDB; idx += 256)
            g_kn2[100 * LDB + idx] = __float2bfloat16(0.0f);
    }
}

// ================= main kernel: M=64, 256 threads, 2 CTAs/SM =================
#define OFF_WC 33792
#define OFF_KB 67584
#define DYN_SM 101376

__global__ void __launch_bounds__(256, 2)
kernMain(const float* __restrict__ feats,
         const float* __restrict__ mask,
         const float* __restrict__ bq) {
    extern __shared__ char smx[];
    __nv_bfloat16* fh = reinterpret_cast<__nv_bfloat16*>(smx);            // feats_hi -> q_hi -> att
    __nv_bfloat16* wc = reinterpret_cast<__nv_bfloat16*>(smx + OFF_WC);   // E chunks; lower half -> q_lo
    __nv_bfloat16* kb = reinterpret_cast<__nv_bfloat16*>(smx + OFF_KB);   // kn pass buffer
    float* att = reinterpret_cast<float*>(smx);                            // [64][108] overlay
    __shared__ float mask_s[MR];
    __shared__ float bq_s[C_];
    __shared__ float rinv_s[MR];
    __shared__ float ssq_s[MR][4];
    __shared__ float mf_s[2][C_];
    __shared__ float as2[2][104];

    const int tid = threadIdx.x, wid = tid >> 5, lane = tid & 31;
    const int blk = blockIdx.x, b = blk >> 5, n0 = (blk & 31) * MR;
    const int wm = wid & 1;      // 32-row half
    const int wn = wid >> 1;     // 0..3
    const uint32_t FH = smem_u32(fh), WCa = smem_u32(wc), KBa = smem_u32(kb);

    // ---- phase 1: feats -> bf16 hi in smem; mask; bq ----
    {
        const int r = tid >> 2, seg = tid & 3;
        const float4* src = reinterpret_cast<const float4*>(
            feats + ((size_t)b * N_ + n0 + r) * C_ + seg * 64);
        uint32_t* dh = reinterpret_cast<uint32_t*>(fh + r * LDB + seg * 64);
#pragma unroll
        for (int i = 0; i < 16; i++) {
            float4 v = src[i];
            dh[2 * i]     = cvt2hi(v.x, v.y);
            dh[2 * i + 1] = cvt2hi(v.z, v.w);
        }
    }
    if (tid < MR) mask_s[tid] = mask[(size_t)b * N_ + n0 + tid];
    if (tid < C_) bq_s[tid] = bq[tid];
    __syncthreads();

    // ---- phase 1b: maskfeat + masksum from gmem fp32 (exact) ----
    {
        const int cp = tid & 127, half = tid >> 7;
        const float2* f2 = reinterpret_cast<const float2*>(
            feats + ((size_t)b * N_ + n0 + half * 32) * C_) + cp;
        float a0 = 0.0f, a1 = 0.0f;
#pragma unroll 8
        for (int r = 0; r < 32; r++) {
            float m = mask_s[half * 32 + r];
            float2 v = f2[(size_t)r * (C_ / 2)];
            a0 = fmaf(m, v.x, a0);
            a1 = fmaf(m, v.y, a1);
        }
        mf_s[half][2 * cp]     = a0;
        mf_s[half][2 * cp + 1] = a1;
        if (tid == 0) {
            float s = 0.0f;
            for (int r = 0; r < MR; r++) s += mask_s[r];
            g_masksum_part[blk] = s;
        }
    }
    __syncthreads();
    if (tid < C_) g_maskfeat_part[blk * C_ + tid] = mf_s[0][tid] + mf_s[1][tid];

    // ---- phase 2: q GEMM  C1 = feats_hi @ E^T  (M64 x N256, K256; 2 N-chunks of 128) ----
    float acc[2][2][4][4];
#pragma unroll
    for (int c = 0; c < 2; c++)
#pragma unroll
        for (int mt = 0; mt < 2; mt++)
#pragma unroll
            for (int nt = 0; nt < 4; nt++)
#pragma unroll
                for (int j = 0; j < 4; j++) acc[c][mt][nt][j] = 0.0f;

    for (int c = 0; c < 2; c++) {
        __syncthreads();
        {
            const uint4* s = reinterpret_cast<const uint4*>(g_E + c * 128 * LDB);
            uint4* d = reinterpret_cast<uint4*>(wc);
            for (int i = tid; i < 4224; i += 256) d[i] = s[i];
        }
        __syncthreads();
#pragma unroll 4
        for (int k0 = 0; k0 < 256; k0 += 16) {
            uint32_t a[2][4];
#pragma unroll
            for (int mt = 0; mt < 2; mt++) {
                uint32_t addr = FH + (uint32_t)(wm * 32 + mt * 16 + (lane & 15)) * ROWB
                              + (uint32_t)(k0 + (lane >> 4) * 8) * 2u;
                ldsm4(a[mt][0], a[mt][1], a[mt][2], a[mt][3], addr);
            }
            uint32_t bf[2][4];
#pragma unroll
            for (int np = 0; np < 2; np++) {
                uint32_t addr = WCa + (uint32_t)(wn * 32 + np * 16 + (lane >> 4) * 8 + (lane & 7)) * ROWB
                              + (uint32_t)(k0 + ((lane >> 3) & 1) * 8) * 2u;
                ldsm4(bf[np][0], bf[np][1], bf[np][2], bf[np][3], addr);
            }
#pragma unroll
            for (int mt = 0; mt < 2; mt++)
#pragma unroll
                for (int nt = 0; nt < 4; nt++)
                    mma16816(acc[c][mt][nt], a[mt][0], a[mt][1], a[mt][2], a[mt][3],
                             bf[nt >> 1][(nt & 1) * 2], bf[nt >> 1][(nt & 1) * 2 + 1]);
        }
    }
    __syncthreads();   // all GEMM smem reads done before overwrite

    // ---- phase 3: q epilogue: q = C1 + f(gmem fp32) + bq; ssq; split -> fh(hi)/wc(lo) ----
    {
        float ssq[2][2];
#pragma unroll
        for (int mt = 0; mt < 2; mt++) { ssq[mt][0] = 0.0f; ssq[mt][1] = 0.0f; }
#pragma unroll
        for (int c = 0; c < 2; c++)
#pragma unroll
            for (int mt = 0; mt < 2; mt++)
#pragma unroll
                for (int nt = 0; nt < 4; nt++) {
                    const int n  = c * 128 + wn * 32 + nt * 8 + (lane & 3) * 2;
                    const int m0 = wm * 32 + mt * 16 + (lane >> 2);
#pragma unroll
                    for (int hh = 0; hh < 2; hh++) {
                        const int m = m0 + hh * 8;
                        float2 f = *reinterpret_cast<const float2*>(
                            feats + ((size_t)b * N_ + n0 + m) * C_ + n);
                        float q0 = acc[c][mt][nt][hh * 2]     + f.x + bq_s[n];
                        float q1 = acc[c][mt][nt][hh * 2 + 1] + f.y + bq_s[n + 1];
                        ssq[mt][hh] = fmaf(q0, q0, fmaf(q1, q1, ssq[mt][hh]));
                        uint32_t qh, ql;
                        split2(q0, q1, qh, ql);
                        *reinterpret_cast<uint32_t*>(fh + m * LDB + n) = qh;
                        *reinterpret_cast<uint32_t*>(wc + m * LDB + n) = ql;
                    }
                }
#pragma unroll
        for (int mt = 0; mt < 2; mt++)
#pragma unroll
            for (int hh = 0; hh < 2; hh++) {
                float v = ssq[mt][hh];
                v += __shfl_xor_sync(0xffffffffu, v, 1);
                v += __shfl_xor_sync(0xffffffffu, v, 2);
                if ((lane & 3) == 0)
                    ssq_s[wm * 32 + mt * 16 + (lane >> 2) + hh * 8][wn] = v;
            }
    }
    __syncthreads();
    if (tid < MR)
        rinv_s[tid] = 1.0f / fmaxf(sqrtf(ssq_s[tid][0] + ssq_s[tid][1]
                                       + ssq_s[tid][2] + ssq_s[tid][3]), 1e-12f);

    // ---- phase 4: logits GEMM, 2 passes of 64 kn rows, 2-product (q_hi+q_lo)@kn_hi ----
    float acc2[2][2][2][4];
#pragma unroll
    for (int p = 0; p < 2; p++)
#pragma unroll
        for (int mt = 0; mt < 2; mt++)
#pragma unroll
            for (int nt = 0; nt < 2; nt++)
#pragma unroll
                for (int j = 0; j < 4; j++) acc2[p][mt][nt][j] = 0.0f;

    for (int p = 0; p < 2; p++) {
        __syncthreads();
        {
            const uint4* s = reinterpret_cast<const uint4*>(g_kn2 + p * 64 * LDB);
            uint4* d = reinterpret_cast<uint4*>(kb);
            for (int i = tid; i < 2112; i += 256) d[i] = s[i];
        }
        __syncthreads();
#pragma unroll 2
        for (int k0 = 0; k0 < 256; k0 += 16) {
            uint32_t ah[2][4], al[2][4];
#pragma unroll
            for (int mt = 0; mt < 2; mt++) {
                uint32_t ro = (uint32_t)(wm * 32 + mt * 16 + (lane & 15)) * ROWB
                            + (uint32_t)(k0 + (lane >> 4) * 8) * 2u;
                ldsm4(ah[mt][0], ah[mt][1], ah[mt][2], ah[mt][3], FH + ro);
                ldsm4(al[mt][0], al[mt][1], al[mt][2], al[mt][3], WCa + ro);
            }
            uint32_t bh[4];
            {
                uint32_t addr = KBa + (uint32_t)(wn * 16 + (lane >> 4) * 8 + (lane & 7)) * ROWB
                              + (uint32_t)(k0 + ((lane >> 3) & 1) * 8) * 2u;
                ldsm4(bh[0], bh[1], bh[2], bh[3], addr);
            }
#pragma unroll
            for (int mt = 0; mt < 2; mt++)
#pragma unroll
                for (int nt = 0; nt < 2; nt++) {
                    float* cc = acc2[p][mt][nt];
                    mma16816(cc, ah[mt][0], ah[mt][1], ah[mt][2], ah[mt][3],
                             bh[nt * 2], bh[nt * 2 + 1]);
                    mma16816(cc, al[mt][0], al[mt][1], al[mt][2], al[mt][3],
                             bh[nt * 2], bh[nt * 2 + 1]);
                }
        }
    }
    __syncthreads();   // fh reads done; att overlay safe

    // ---- phase 5: att write (scaled by rinv) ----
#pragma unroll
    for (int p = 0; p < 2; p++)
#pragma unroll
        for (int mt = 0; mt < 2; mt++)
#pragma unroll
            for (int nt = 0; nt < 2; nt++) {
                const int n  = p * 64 + wn * 16 + nt * 8 + (lane & 3) * 2;
                const int m0 = wm * 32 + mt * 16 + (lane >> 2);
#pragma unroll
                for (int hh = 0; hh < 2; hh++) {
                    const int m = m0 + hh * 8;
                    const float ri = rinv_s[m];
                    if (n < NB_)     att[m * 108 + n]     = acc2[p][mt][nt][hh * 2]     * ri;
                    if (n + 1 < NB_) att[m * 108 + n + 1] = acc2[p][mt][nt][hh * 2 + 1] * ri;
                }
            }
    __syncthreads();

    // ---- phase 6: softmax + mask fold (4 threads per row) ----
    {
        const int r = tid >> 2, s = tid & 3;
        float* row = att + r * 108;
        float mx = -1e30f;
        for (int j = s; j < NB_; j += 4) mx = fmaxf(mx, row[j]);
        mx = fmaxf(mx, __shfl_xor_sync(0xffffffffu, mx, 1));
        mx = fmaxf(mx, __shfl_xor_sync(0xffffffffu, mx, 2));
        float sum = 0.0f;
        for (int j = s; j < NB_; j += 4) { float e = __expf(row[j] - mx); row[j] = e; sum += e; }
        sum += __shfl_xor_sync(0xffffffffu, sum, 1);
        sum += __shfl_xor_sync(0xffffffffu, sum, 2);
        const float sc = mask_s[r] / sum;
        for (int j = s; j < NB_; j += 4) row[j] *= sc;
    }
    __syncthreads();

    // ---- phase 7: attsum partials ----
    {
        const int c = tid & 127, half = tid >> 7;
        if (c < NB_) {
            float a = 0.0f;
#pragma unroll 8
            for (int r = half * 32; r < half * 32 + 32; r++) a += att[r * 108 + c];
            as2[half][c] = a;
        }
    }
    __syncthreads();
    if (tid < NB_)
        g_attsum_part[blk * NB_ + tid] = as2[0][tid] + as2[1][tid];
}

// ================= kernel C: reduce partials + combine (512 thr) =================
__global__ void kernC(const float* __restrict__ base,
                      const float* __restrict__ w_avg,
                      const float* __restrict__ w_att,
                      float* __restrict__ out) {
    __shared__ float as_s[NB_];
    __shared__ float mf2[2][256];
    __shared__ float asp[2][NB_];
    __shared__ float dsh;
    const int b = blockIdx.x, tid = threadIdx.x;
    const int c = tid & 255, h = tid >> 8;

    if (tid == 0) {
        float s = 0.0f;
        for (int t = 0; t < NT2; t++) s += g_masksum_part[b * NT2 + t];
        dsh = fmaxf(s, 1e-12f);
    }
    if (c < NB_) {
        float s = 0.0f;
        for (int t = h * 16; t < h * 16 + 16; t++)
            s += g_attsum_part[(b * NT2 + t) * NB_ + c];
        asp[h][c] = s;
    }
    {
        float s = 0.0f;
        for (int t = h * 16; t < h * 16 + 16; t++)
            s += g_maskfeat_part[(b * NT2 + t) * C_ + c];
        mf2[h][c] = s;
    }
    __syncthreads();
    if (tid < NB_) as_s[tid] = asp[0][tid] + asp[1][tid];
    __syncthreads();
    if (tid < 256) {
        float mf = mf2[0][tid] + mf2[1][tid];
        float n2 = 0.0f;
#pragma unroll 4
        for (int m = 0; m < NB_; m++) n2 = fmaf(as_s[m], base[m * C_ + tid], n2);
        float inv = 1.0f / dsh;
        out[b * C_ + tid] = 0.5f * (mf * inv * w_avg[tid] + n2 * inv * w_att[tid]);
    }
}

// ================= launch =================
extern "C" void kernel_launch(void* const* d_in, const int* in_sizes, int n_in,
                              void* d_out, int out_size) {
    const float* base  = (const float*)d_in[0];
    const float* feats = (const float*)d_in[1];
    const float* mask  = (const float*)d_in[2];
    const float* Wq    = (const float*)d_in[3];
    const float* bq    = (const float*)d_in[4];
    const float* Wk    = (const float*)d_in[5];
    const float* bk    = (const float*)d_in[6];
    const float* w_avg = (const float*)d_in[7];
    const float* w_att = (const float*)d_in[8];
    float* out = (float*)d_out;

    cudaFuncSetAttribute(kernMain, cudaFuncAttributeMaxDynamicSharedMemorySize, DYN_SM);

    kernAP<<<109, 256>>>(base, Wk, bk, Wq);
    kernMain<<<NBLK, 256, DYN_SM>>>(feats, mask, bq);
    kernC<<<B_, 512>>>(base, w_avg, w_att, out);
}

// round 7
// speedup vs baseline: 4.7795x; 1.0572x over previous
#include <cuda_runtime.h>
#include <cuda_bf16.h>
#include <cuda_fp8.h>
#include <cstdint>
#include <math.h>

#define B_    64
#define N_    2048
#define C_    256
#define NB_   100
#define MR    64              // rows per CTA
#define NT2   32              // tiles per batch
#define NBLK  (B_ * NT2)      // 2048
#define LDB   264             // bf16 elems per padded row
#define ROWB  (LDB * 2)       // 528 bytes
#define LD8   272             // fp8 bytes per padded row
#define ESCALE   256.0f
#define INV_ESC  (1.0f / 256.0f)

// ---------------- device scratch ----------------
__device__ __align__(16) unsigned char g_E8[256 * LD8];    // (Wq-I)*256, e4m3, [n][k]
__device__ __align__(16) __nv_bfloat16 g_kn2[128 * LDB];   // kn bf16, rows 100..127 zero
__device__ float g_attsum_part[NBLK * NB_];
__device__ float g_maskfeat_part[NBLK * C_];
__device__ float g_masksum_part[NBLK];

// ---------------- helpers ----------------
__device__ __forceinline__ uint32_t smem_u32(const void* p) {
    uint32_t a;
    asm("{ .reg .u64 t; cvta.to.shared.u64 t, %1; cvt.u32.u64 %0, t; }" : "=r"(a) : "l"(p));
    return a;
}
__device__ __forceinline__ void ldsm4(uint32_t& r0, uint32_t& r1, uint32_t& r2, uint32_t& r3,
                                      uint32_t addr) {
    asm volatile("ldmatrix.sync.aligned.m8n8.x4.shared.b16 {%0,%1,%2,%3}, [%4];"
                 : "=r"(r0), "=r"(r1), "=r"(r2), "=r"(r3) : "r"(addr));
}
__device__ __forceinline__ void mma16816(float* c, uint32_t a0, uint32_t a1, uint32_t a2,
                                         uint32_t a3, uint32_t b0, uint32_t b1) {
    asm volatile("mma.sync.aligned.m16n8k16.row.col.f32.bf16.bf16.f32 "
                 "{%0,%1,%2,%3}, {%4,%5,%6,%7}, {%8,%9}, {%0,%1,%2,%3};"
                 : "+f"(c[0]), "+f"(c[1]), "+f"(c[2]), "+f"(c[3])
                 : "r"(a0), "r"(a1), "r"(a2), "r"(a3), "r"(b0), "r"(b1));
}
__device__ __forceinline__ void mmafp8(float* c, uint32_t a0, uint32_t a1, uint32_t a2,
                                       uint32_t a3, uint32_t b0, uint32_t b1) {
    asm volatile("mma.sync.aligned.m16n8k32.row.col.f32.e4m3.e4m3.f32 "
                 "{%0,%1,%2,%3}, {%4,%5,%6,%7}, {%8,%9}, {%0,%1,%2,%3};"
                 : "+f"(c[0]), "+f"(c[1]), "+f"(c[2]), "+f"(c[3])
                 : "r"(a0), "r"(a1), "r"(a2), "r"(a3), "r"(b0), "r"(b1));
}
__device__ __forceinline__ void split2(float x, float y, uint32_t& hi, uint32_t& lo) {
    __nv_bfloat16 hx = __float2bfloat16(x);
    __nv_bfloat16 hy = __float2bfloat16(y);
    __nv_bfloat16 lx = __float2bfloat16(x - __bfloat162float(hx));
    __nv_bfloat16 ly = __float2bfloat16(y - __bfloat162float(hy));
    __nv_bfloat162 H = __halves2bfloat162(hx, hy);
    __nv_bfloat162 L = __halves2bfloat162(lx, ly);
    hi = *reinterpret_cast<uint32_t*>(&H);
    lo = *reinterpret_cast<uint32_t*>(&L);
}
// pack 4 floats -> 4 e4m3 bytes (x lowest)
__device__ __forceinline__ uint32_t pack4_e4m3(float x, float y, float z, float w) {
    unsigned short lo, hi;
    asm("cvt.rn.satfinite.e4m3x2.f32 %0, %1, %2;" : "=h"(lo) : "f"(y), "f"(x));
    asm("cvt.rn.satfinite.e4m3x2.f32 %0, %1, %2;" : "=h"(hi) : "f"(w), "f"(z));
    return (uint32_t)lo | ((uint32_t)hi << 16);
}

// ========== kernel AP: kn (blocks 0-99), E8 pack (100-107), kn pad (108) ==========
__global__ void kernAP(const float* __restrict__ base,
                       const float* __restrict__ Wk,
                       const float* __restrict__ bk,
                       const float* __restrict__ Wq) {
    const int bb = blockIdx.x, tid = threadIdx.x;
    if (bb < NB_) {
        __shared__ float bs[C_];
        __shared__ float ks[C_];
        __shared__ float red[C_];
        const int wid = tid >> 5, lane = tid & 31;
        bs[tid] = base[bb * C_ + tid];
        __syncthreads();
        for (int c = wid; c < C_; c += 8) {
            const float4* w = reinterpret_cast<const float4*>(Wk + (size_t)c * C_);
            float p = 0.0f;
#pragma unroll
            for (int i = 0; i < 2; i++) {
                int j = lane + i * 32;
                float4 v = w[j];
                p = fmaf(bs[4 * j + 0], v.x, p);
                p = fmaf(bs[4 * j + 1], v.y, p);
                p = fmaf(bs[4 * j + 2], v.z, p);
                p = fmaf(bs[4 * j + 3], v.w, p);
            }
#pragma unroll
            for (int o = 16; o; o >>= 1) p += __shfl_xor_sync(0xffffffffu, p, o);
            if (lane == 0) ks[c] = p + bk[c];
        }
        __syncthreads();
        red[tid] = ks[tid] * ks[tid];
        __syncthreads();
        for (int s = 128; s; s >>= 1) {
            if (tid < s) red[tid] += red[tid + s];
            __syncthreads();
        }
        g_kn2[bb * LDB + tid] = __float2bfloat16(ks[tid] / fmaxf(sqrtf(red[0]), 1e-12f));
    } else if (bb < 108) {
        // E8 = (Wq - I) * 256 in e4m3, rows of LD8 bytes (pad zero)
        uint32_t* dst = reinterpret_cast<uint32_t*>(g_E8);
        for (int u = (bb - 100) * 256 + tid; u < 256 * (LD8 / 4); u += 8 * 256) {
            int n = u / (LD8 / 4), j = u - n * (LD8 / 4);
            int k4 = j * 4;
            uint32_t w = 0;
            if (k4 < 256) {
                float4 v = *reinterpret_cast<const float4*>(Wq + n * 256 + k4);
                float e0 = (v.x - (n == k4 + 0 ? 1.0f : 0.0f)) * ESCALE;
                float e1 = (v.y - (n == k4 + 1 ? 1.0f : 0.0f)) * ESCALE;
                float e2 = (v.z - (n == k4 + 2 ? 1.0f : 0.0f)) * ESCALE;
                float e3 = (v.w - (n == k4 + 3 ? 1.0f : 0.0f)) * ESCALE;
                w = pack4_e4m3(e0, e1, e2, e3);
            }
            dst[u] = w;
        }
    } else {
        for (int idx = tid; idx < 28 * LDB; idx += 256)
            g_kn2[100 * LDB + idx] = __float2bfloat16(0.0f);
    }
}

// ========== main kernel: fp8 q GEMM + bf16-split logits, 2 CTAs/SM ==========
#define OFF_R2 33792     // E8 chunk / q_lo
#define OFF_R3 68608     // q_hi / att
#define DYN_SM 102400

__global__ void __launch_bounds__(256, 2)
kernMain(const float* __restrict__ feats,
         const float* __restrict__ mask,
         const float* __restrict__ bq) {
    extern __shared__ char smx[];
    unsigned char* f8 = reinterpret_cast<unsigned char*>(smx);             // fp8 f; later kn
    __nv_bfloat16*  kb = reinterpret_cast<__nv_bfloat16*>(smx);
    unsigned char* e8 = reinterpret_cast<unsigned char*>(smx + OFF_R2);    // E chunk; later q_lo
    __nv_bfloat16*  ql = reinterpret_cast<__nv_bfloat16*>(smx + OFF_R2);
    __nv_bfloat16*  qh = reinterpret_cast<__nv_bfloat16*>(smx + OFF_R3);   // q_hi; later att
    float* att = reinterpret_cast<float*>(smx + OFF_R3);
    __shared__ float mask_s[MR];
    __shared__ float bq_s[C_];
    __shared__ float rinv_s[MR];
    __shared__ float ssq_s[MR][4];
    __shared__ float mf_s[2][C_];
    __shared__ float as2[2][104];

    const int tid = threadIdx.x, wid = tid >> 5, lane = tid & 31;
    const int blk = blockIdx.x, b = blk >> 5, n0 = (blk & 31) * MR;
    const int wm = wid & 1;      // 32-row half
    const int wn = wid >> 1;     // 0..3
    const uint32_t F8 = smem_u32(f8), E8a = smem_u32(e8);
    const uint32_t QH = smem_u32(qh), QL = smem_u32(ql), KN = smem_u32(kb);

    // ---- phase 1: feats -> e4m3 in smem ----
    {
        const int r = tid >> 2, seg = tid & 3;
        const float4* src = reinterpret_cast<const float4*>(
            feats + ((size_t)b * N_ + n0 + r) * C_ + seg * 64);
        uint32_t* dst = reinterpret_cast<uint32_t*>(f8 + r * LD8 + seg * 64);
#pragma unroll
        for (int i = 0; i < 16; i++) {
            float4 v = src[i];
            dst[i] = pack4_e4m3(v.x, v.y, v.z, v.w);
        }
    }
    if (tid < MR) mask_s[tid] = mask[(size_t)b * N_ + n0 + tid];
    if (tid < C_) bq_s[tid] = bq[tid];
    __syncthreads();

    // ---- phase 1b: maskfeat + masksum from gmem fp32 (exact) ----
    {
        const int cp = tid & 127, half = tid >> 7;
        const float2* f2 = reinterpret_cast<const float2*>(
            feats + ((size_t)b * N_ + n0 + half * 32) * C_) + cp;
        float a0 = 0.0f, a1 = 0.0f;
#pragma unroll 8
        for (int r = 0; r < 32; r++) {
            float m = mask_s[half * 32 + r];
            float2 v = f2[(size_t)r * (C_ / 2)];
            a0 = fmaf(m, v.x, a0);
            a1 = fmaf(m, v.y, a1);
        }
        mf_s[half][2 * cp]     = a0;
        mf_s[half][2 * cp + 1] = a1;
        if (tid == 0) {
            float s = 0.0f;
            for (int r = 0; r < MR; r++) s += mask_s[r];
            g_masksum_part[blk] = s;
        }
    }
    __syncthreads();
    if (tid < C_) g_maskfeat_part[blk * C_ + tid] = mf_s[0][tid] + mf_s[1][tid];

    // ---- phase 2: fp8 q GEMM  C1 = f8 @ E8^T  (M64 x N256, K256; 2 N-chunks) ----
    float acc[2][2][4][4];
#pragma unroll
    for (int c = 0; c < 2; c++)
#pragma unroll
        for (int mt = 0; mt < 2; mt++)
#pragma unroll
            for (int nt = 0; nt < 4; nt++)
#pragma unroll
                for (int j = 0; j < 4; j++) acc[c][mt][nt][j] = 0.0f;

    for (int c = 0; c < 2; c++) {
        __syncthreads();
        {
            const uint4* s = reinterpret_cast<const uint4*>(g_E8 + c * 128 * LD8);
            uint4* d = reinterpret_cast<uint4*>(e8);
            for (int i = tid; i < 128 * LD8 / 16; i += 256) d[i] = s[i];
        }
        __syncthreads();
#pragma unroll 4
        for (int ks = 0; ks < 8; ks++) {
            const uint32_t k0b = ks * 32;
            uint32_t a[2][4];
#pragma unroll
            for (int mt = 0; mt < 2; mt++) {
                uint32_t addr = F8 + (uint32_t)(wm * 32 + mt * 16 + (lane & 15)) * LD8
                              + k0b + (lane >> 4) * 16u;
                ldsm4(a[mt][0], a[mt][1], a[mt][2], a[mt][3], addr);
            }
            uint32_t bf[2][4];
#pragma unroll
            for (int np = 0; np < 2; np++) {
                uint32_t addr = E8a + (uint32_t)(wn * 32 + np * 16 + (lane >> 4) * 8 + (lane & 7)) * LD8
                              + k0b + ((lane >> 3) & 1) * 16u;
                ldsm4(bf[np][0], bf[np][1], bf[np][2], bf[np][3], addr);
            }
#pragma unroll
            for (int mt = 0; mt < 2; mt++)
#pragma unroll
                for (int nt = 0; nt < 4; nt++)
                    mmafp8(acc[c][mt][nt], a[mt][0], a[mt][1], a[mt][2], a[mt][3],
                           bf[nt >> 1][(nt & 1) * 2], bf[nt >> 1][(nt & 1) * 2 + 1]);
        }
    }
    __syncthreads();   // GEMM reads done; f8/e8 regions may be overwritten

    // ---- phase 3: q = acc/256 + f(gmem fp32) + bq; ssq; split -> qh / ql ----
    {
        float ssq[2][2];
#pragma unroll
        for (int mt = 0; mt < 2; mt++) { ssq[mt][0] = 0.0f; ssq[mt][1] = 0.0f; }
#pragma unroll
        for (int c = 0; c < 2; c++)
#pragma unroll
            for (int mt = 0; mt < 2; mt++)
#pragma unroll
                for (int nt = 0; nt < 4; nt++) {
                    const int n  = c * 128 + wn * 32 + nt * 8 + (lane & 3) * 2;
                    const int m0 = wm * 32 + mt * 16 + (lane >> 2);
#pragma unroll
                    for (int hh = 0; hh < 2; hh++) {
                        const int m = m0 + hh * 8;
                        float2 f = *reinterpret_cast<const float2*>(
                            feats + ((size_t)b * N_ + n0 + m) * C_ + n);
                        float q0 = acc[c][mt][nt][hh * 2]     * INV_ESC + f.x + bq_s[n];
                        float q1 = acc[c][mt][nt][hh * 2 + 1] * INV_ESC + f.y + bq_s[n + 1];
                        ssq[mt][hh] = fmaf(q0, q0, fmaf(q1, q1, ssq[mt][hh]));
                        uint32_t h, l;
                        split2(q0, q1, h, l);
                        *reinterpret_cast<uint32_t*>(qh + m * LDB + n) = h;
                        *reinterpret_cast<uint32_t*>(ql + m * LDB + n) = l;
                    }
                }
#pragma unroll
        for (int mt = 0; mt < 2; mt++)
#pragma unroll
            for (int hh = 0; hh < 2; hh++) {
                float v = ssq[mt][hh];
                v += __shfl_xor_sync(0xffffffffu, v, 1);
                v += __shfl_xor_sync(0xffffffffu, v, 2);
                if ((lane & 3) == 0)
                    ssq_s[wm * 32 + mt * 16 + (lane >> 2) + hh * 8][wn] = v;
            }
    }
    __syncthreads();
    if (tid < MR)
        rinv_s[tid] = 1.0f / fmaxf(sqrtf(ssq_s[tid][0] + ssq_s[tid][1]
                                       + ssq_s[tid][2] + ssq_s[tid][3]), 1e-12f);

    // ---- phase 4: logits GEMM, 2 passes of 64 kn rows, (q_hi+q_lo)@kn ----
    float acc2[2][2][2][4];
#pragma unroll
    for (int p = 0; p < 2; p++)
#pragma unroll
        for (int mt = 0; mt < 2; mt++)
#pragma unroll
            for (int nt = 0; nt < 2; nt++)
#pragma unroll
                for (int j = 0; j < 4; j++) acc2[p][mt][nt][j] = 0.0f;

    for (int p = 0; p < 2; p++) {
        __syncthreads();
        {
            const uint4* s = reinterpret_cast<const uint4*>(g_kn2 + p * 64 * LDB);
            uint4* d = reinterpret_cast<uint4*>(kb);
            for (int i = tid; i < 2112; i += 256) d[i] = s[i];
        }
        __syncthreads();
#pragma unroll 2
        for (int k0 = 0; k0 < 256; k0 += 16) {
            uint32_t ah[2][4], al[2][4];
#pragma unroll
            for (int mt = 0; mt < 2; mt++) {
                uint32_t ro = (uint32_t)(wm * 32 + mt * 16 + (lane & 15)) * ROWB
                            + (uint32_t)(k0 + (lane >> 4) * 8) * 2u;
                ldsm4(ah[mt][0], ah[mt][1], ah[mt][2], ah[mt][3], QH + ro);
                ldsm4(al[mt][0], al[mt][1], al[mt][2], al[mt][3], QL + ro);
            }
            uint32_t bh[4];
            {
                uint32_t addr = KN + (uint32_t)(wn * 16 + (lane >> 4) * 8 + (lane & 7)) * ROWB
                              + (uint32_t)(k0 + ((lane >> 3) & 1) * 8) * 2u;
                ldsm4(bh[0], bh[1], bh[2], bh[3], addr);
            }
#pragma unroll
            for (int mt = 0; mt < 2; mt++)
#pragma unroll
                for (int nt = 0; nt < 2; nt++) {
                    float* cc = acc2[p][mt][nt];
                    mma16816(cc, ah[mt][0], ah[mt][1], ah[mt][2], ah[mt][3],
                             bh[nt * 2], bh[nt * 2 + 1]);
                    mma16816(cc, al[mt][0], al[mt][1], al[mt][2], al[mt][3],
                             bh[nt * 2], bh[nt * 2 + 1]);
                }
        }
    }
    __syncthreads();   // qh reads done; att overlay safe

    // ---- phase 5: att write (scaled by rinv) ----
#pragma unroll
    for (int p = 0; p < 2; p++)
#pragma unroll
        for (int mt = 0; mt < 2; mt++)
#pragma unroll
            for (int nt = 0; nt < 2; nt++) {
                const int n  = p * 64 + wn * 16 + nt * 8 + (lane & 3) * 2;
                const int m0 = wm * 32 + mt * 16 + (lane >> 2);
#pragma unroll
                for (int hh = 0; hh < 2; hh++) {
                    const int m = m0 + hh * 8;
                    const float ri = rinv_s[m];
                    if (n < NB_)     att[m * 108 + n]     = acc2[p][mt][nt][hh * 2]     * ri;
                    if (n + 1 < NB_) att[m * 108 + n + 1] = acc2[p][mt][nt][hh * 2 + 1] * ri;
                }
            }
    __syncthreads();

    // ---- phase 6: softmax + mask fold (4 threads per row) ----
    {
        const int r = tid >> 2, s = tid & 3;
        float* row = att + r * 108;
        float mx = -1e30f;
        for (int j = s; j < NB_; j += 4) mx = fmaxf(mx, row[j]);
        mx = fmaxf(mx, __shfl_xor_sync(0xffffffffu, mx, 1));
        mx = fmaxf(mx, __shfl_xor_sync(0xffffffffu, mx, 2));
        float sum = 0.0f;
        for (int j = s; j < NB_; j += 4) { float e = __expf(row[j] - mx); row[j] = e; sum += e; }
        sum += __shfl_xor_sync(0xffffffffu, sum, 1);
        sum += __shfl_xor_sync(0xffffffffu, sum, 2);
        const float sc = mask_s[r] / sum;
        for (int j = s; j < NB_; j += 4) row[j] *= sc;
    }
    __syncthreads();

    // ---- phase 7: attsum partials ----
    {
        const int c = tid & 127, half = tid >> 7;
        if (c < NB_) {
            float a = 0.0f;
#pragma unroll 8
            for (int r = half * 32; r < half * 32 + 32; r++) a += att[r * 108 + c];
            as2[half][c] = a;
        }
    }
    __syncthreads();
    if (tid < NB_)
        g_attsum_part[blk * NB_ + tid] = as2[0][tid] + as2[1][tid];
}

// ========== kernel C: reduce partials + combine (128 blocks) ==========
__global__ void kernC(const float* __restrict__ base,
                      const float* __restrict__ w_avg,
                      const float* __restrict__ w_att,
                      float* __restrict__ out) {
    __shared__ float as_s[NB_];
    __shared__ float dsh;
    const int b = blockIdx.x >> 1, side = blockIdx.x & 1, tid = threadIdx.x;

    if (tid >= 128 && tid < 128 + NB_) {
        const int c = tid - 128;
        float s = 0.0f;
#pragma unroll 8
        for (int t = 0; t < NT2; t++) s += g_attsum_part[(b * NT2 + t) * NB_ + c];
        as_s[c] = s;
    }
    if (tid == 0) {
        float s = 0.0f;
        for (int t = 0; t < NT2; t++) s += g_masksum_part[b * NT2 + t];
        dsh = fmaxf(s, 1e-12f);
    }
    float mf = 0.0f;
    const int c = side * 128 + (tid & 127);
    if (tid < 128) {
#pragma unroll 8
        for (int t = 0; t < NT2; t++) mf += g_maskfeat_part[(b * NT2 + t) * C_ + c];
    }
    __syncthreads();
    if (tid < 128) {
        float n2 = 0.0f;
#pragma unroll 4
        for (int m = 0; m < NB_; m++) n2 = fmaf(as_s[m], base[m * C_ + c], n2);
        float inv = 1.0f / dsh;
        out[b * C_ + c] = 0.5f * (mf * inv * w_avg[c] + n2 * inv * w_att[c]);
    }
}

// ========== launch ==========
extern "C" void kernel_launch(void* const* d_in, const int* in_sizes, int n_in,
                              void* d_out, int out_size) {
    const float* base  = (const float*)d_in[0];
    const float* feats = (const float*)d_in[1];
    const float* mask  = (const float*)d_in[2];
    const float* Wq    = (const float*)d_in[3];
    const float* bq    = (const float*)d_in[4];
    const float* Wk    = (const float*)d_in[5];
    const float* bk    = (const float*)d_in[6];
    const float* w_avg = (const float*)d_in[7];
    const float* w_att = (const float*)d_in[8];
    float* out = (float*)d_out;

    cudaFuncSetAttribute(kernMain, cudaFuncAttributeMaxDynamicSharedMemorySize, DYN_SM);

    kernAP<<<109, 256>>>(base, Wk, bk, Wq);
    kernMain<<<NBLK, 256, DYN_SM>>>(feats, mask, bq);
    kernC<<<128, 256>>>(base, w_avg, w_att, out);
}